// round 9
// baseline (speedup 1.0000x reference)
#include <cuda_runtime.h>
#include <cuda_fp16.h>
#include <cstdint>
#include <math.h>

// Problem constants
#define NB   4
#define NH   66
#define NW   66
#define NC   32
#define NF   64
#define HO   64
#define WO   64

// GEMM: per channel K = 176 (9 cij * 18 slots = 162 used, pad to 11 k16-steps)
#define KC        176
#define KI        11                  // k16 steps
#define A_BYTES   (128 * KC * 2)      // 45056 (fragment-major)
#define B_BYTES   (64 * KC * 2)       // 22528 (fragment-major)

// smem offsets
#define SM_A0     0
#define SM_A1     45056
#define SM_B0     90112
#define SM_B1     112640
#define SM_TOTAL  135168

// ---------------------------------------------------------------------------
// Device globals (no allocation allowed)
// B fragment images: [c][ki][ni][lane][4 halves]  (32 * 22528 B = 704 KB)
__device__ __align__(16) __half g_Bfrag[32 * (B_BYTES / 2)];
__device__ __align__(16) float4 g_featP[NC * NB * NH * NW];  // [c][b][h][w]: (t, silu, g-bits, 0)

// ---------------------------------------------------------------------------
__device__ __forceinline__ uint32_t smem_u32(const void* p) {
    uint32_t a;
    asm("{ .reg .u64 t; cvta.to.shared.u64 t, %1; cvt.u32.u64 %0, t; }" : "=r"(a) : "l"(p));
    return a;
}
__device__ __forceinline__ void cp_async16(uint32_t saddr, const void* gptr) {
    asm volatile("cp.async.cg.shared.global [%0], [%1], 16;"
                 :: "r"(saddr), "l"(__cvta_generic_to_global(gptr)) : "memory");
}
__device__ __forceinline__ void cp_commit() {
    asm volatile("cp.async.commit_group;" ::: "memory");
}
__device__ __forceinline__ void mma16816(float* d, const uint32_t* a, const uint32_t* b) {
    asm volatile("mma.sync.aligned.m16n8k16.row.col.f32.f16.f16.f32 "
                 "{%0,%1,%2,%3}, {%4,%5,%6,%7}, {%8,%9}, {%0,%1,%2,%3};"
                 : "+f"(d[0]), "+f"(d[1]), "+f"(d[2]), "+f"(d[3])
                 : "r"(a[0]), "r"(a[1]), "r"(a[2]), "r"(a[3]), "r"(b[0]), "r"(b[1]));
}

// A fragment-major byte address for logical element (pixel r, col):
//   mi=r>>4, row16=r&15, ki=col>>4, kk=col&15
//   lane = ((row16&7)<<2) | ((kk>>1)&3)
//   idx  = (kk&1) | (((row16>>3)&1)<<1) | (((kk>>3)&1)<<2)
//   addr = mi*5632 + ki*512 + lane*16 + idx*2
__device__ __forceinline__ uint32_t a_off(uint32_t base_t, int col) {
    int ki = col >> 4, kk = col & 15;
    return base_t + ki * 512 + (((kk >> 1) & 3) << 4) + ((kk & 1) << 1) + ((kk >> 3) << 3);
}

// ---------------------------------------------------------------------------
// P0: build B fragment images. One half per thread.
__global__ void build_bfrag_kernel(const float* __restrict__ cp,
                                   const float* __restrict__ w_spline,
                                   const float* __restrict__ w_silu)
{
    int idx = blockIdx.x * blockDim.x + threadIdx.x;
    if (idx >= 32 * KI * 8 * 32 * 4) return;
    int b_idx = idx & 3;
    int lane  = (idx >> 2) & 31;
    int ni    = (idx >> 7) & 7;
    int rest  = idx >> 10;
    int ki    = rest % KI;
    int c     = rest / KI;
    int gid   = lane >> 2, tig = lane & 3;
    int f     = ni * 8 + gid;
    int k     = ki * 16 + 2 * tig + (b_idx & 1) + ((b_idx >> 1) << 3);
    float v = 0.0f;
    if (k < 162) {
        int q = k / 18;
        int s = k - 18 * q;
        int iw = (f * 32 + c) * 9 + q;
        v = (s < 17) ? w_spline[iw] * cp[iw * 17 + s] : w_silu[iw];
    }
    g_Bfrag[idx] = __float2half_rn(v);
}

// ---------------------------------------------------------------------------
// P1: planar per-element features: (t, silu, g-as-int-bits, 0) at [c][b][h][w]
__global__ void feat_kernel(const float* __restrict__ x)
{
    int i = blockIdx.x * blockDim.x + threadIdx.x;
    if (i >= NB * NH * NW * NC) return;
    int c   = i & 31;
    int pos = i >> 5;
    float v  = x[i];
    float s  = v / (1.0f + __expf(-v));
    float xc = fminf(1.0f, fmaxf(-1.0f, v));
    float u  = (xc + 1.0f) * 8.0f;
    int   g  = (int)u;
    g = (g > 15) ? 15 : g;
    float t  = u - (float)g;
    g_featP[(size_t)c * (NB * NH * NW) + pos] = make_float4(t, s, __int_as_float(g), 0.0f);
}

// ---------------------------------------------------------------------------
// Main HMMA kernel: 128 blocks x 256 threads (1 block/SM).
// Block = (b, 2 output rows x 64 w) = 128 px. Warp (wm = wid>>1, wn = wid&1):
// M rows [32*wm, +32), N cols [32*wn, +32).
// Pipeline per channel c: wait B(c) -> sync -> prefetch B(c+1) -> MMA(c) -> build(c+1).
__global__ void __launch_bounds__(256, 1)
kan_hmma_kernel(const float* __restrict__ bias, float* __restrict__ out)
{
    extern __shared__ char smem[];
    const uint32_t sbase = smem_u32(smem);
    const int tid  = threadIdx.x;
    const int wid  = tid >> 5;
    const int lane = tid & 31;
    const int blk  = blockIdx.x;
    const int b    = blk >> 5;
    const int h0   = (blk & 31) * 2;

    // zero both A fragment buffers (cols never written stay 0 forever)
    {
        float4* az = (float4*)smem;
#pragma unroll 4
        for (int i = tid; i < (2 * A_BYTES) / 16; i += 256) az[i] = make_float4(0.f, 0.f, 0.f, 0.f);
    }
    // prefetch B(0) into B0
    for (int i = tid; i < B_BYTES / 16; i += 256)
        cp_async16(sbase + SM_B0 + i * 16, (const char*)g_Bfrag + i * 16);
    cp_commit();
    __syncthreads();   // A zeroing visible before scatter

    // scatter config: threads 0-127 -> pixel r, q 0..3; 128-255 -> same r, q 4..8
    const int r     = tid & 127;
    const int qbase = (tid >> 7) ? 4 : 0;
    const int qcnt  = (tid >> 7) ? 5 : 4;
    const int rh    = r >> 6, rw = r & 63;
    const int mi    = r >> 4, row16 = r & 15;
    const uint32_t base_t0 = (uint32_t)(mi * 5632 + ((row16 & 7) << 6) + (((row16 >> 3) & 1) << 2));

    const int wm = wid >> 1, wn = wid & 1;

    float acc[2][4][4];
#pragma unroll
    for (int mt = 0; mt < 2; mt++)
#pragma unroll
        for (int nt = 0; nt < 4; nt++)
#pragma unroll
            for (int e = 0; e < 4; e++) acc[mt][nt][e] = 0.0f;

    uint32_t gpack[2] = {0u, 0u};

    // build A(c) into buffer c&1 (zero stale slots from c-2 first)
    auto build = [&](int c) {
        char* Ab = smem + ((c & 1) ? SM_A1 : SM_A0);
#pragma unroll
        for (int qi = 0; qi < 5; qi++) {
            if (qi >= qcnt) break;
            int q  = qbase + qi;
            int ii = q / 3, jj = q - 3 * ii;
            float4 fv = __ldg(g_featP + ((size_t)(c * NB + b) * NH + (h0 + rh + ii)) * NW + (rw + jj));
            int g = __float_as_int(fv.z);
            if (c >= 2) {
                int gold = (gpack[c & 1] >> (4 * qi)) & 15;
                int oc   = q * 18 + gold;
                *(__half*)(Ab + a_off(base_t0, oc))     = __ushort_as_half((unsigned short)0);
                *(__half*)(Ab + a_off(base_t0, oc + 1)) = __ushort_as_half((unsigned short)0);
            }
            int col0 = q * 18 + g;
            *(__half*)(Ab + a_off(base_t0, col0))        = __float2half_rn(1.0f - fv.x);
            *(__half*)(Ab + a_off(base_t0, col0 + 1))    = __float2half_rn(fv.x);
            *(__half*)(Ab + a_off(base_t0, q * 18 + 17)) = __float2half_rn(fv.y);
            gpack[c & 1] = (gpack[c & 1] & ~(15u << (4 * qi))) | ((uint32_t)g << (4 * qi));
        }
    };

    build(0);

    for (int c = 0; c < 32; c++) {
        const int buf = c & 1;

        // 1) B(c) arrived (it is the only outstanding cp.async group here)
        asm volatile("cp.async.wait_group 0;" ::: "memory");
        // 2) barrier: build(c) visible; MMA(c-1) LDS of opposite buffers retired
        __syncthreads();
        // 3) issue prefetch B(c+1) into the opposite B buffer (now safe to overwrite)
        if (c < 31) {
            uint32_t bdst = sbase + (((c + 1) & 1) ? SM_B1 : SM_B0);
            const char* bsrc = (const char*)g_Bfrag + (size_t)(c + 1) * B_BYTES;
            for (int i = tid; i < B_BYTES / 16; i += 256)
                cp_async16(bdst + i * 16, bsrc + i * 16);
            cp_commit();
        }

        // 4) MMA(c): LDS fragments -> regs, accumulate
        {
            const uint32_t abase = sbase + (buf ? SM_A1 : SM_A0);
            const uint32_t bbase = sbase + (buf ? SM_B1 : SM_B0);
#pragma unroll
            for (int ki = 0; ki < KI; ki++) {
                uint32_t afr[2][4];
#pragma unroll
                for (int mt = 0; mt < 2; mt++) {
                    int mi_t = wm * 2 + mt;
                    uint32_t ad = abase + (uint32_t)((mi_t * KI + ki) * 512 + lane * 16);
                    asm volatile("ld.shared.v4.b32 {%0,%1,%2,%3}, [%4];"
                                 : "=r"(afr[mt][0]), "=r"(afr[mt][1]),
                                   "=r"(afr[mt][2]), "=r"(afr[mt][3]) : "r"(ad));
                }
                uint32_t bfr[4][2];
#pragma unroll
                for (int nt = 0; nt < 4; nt++) {
                    int ni = wn * 4 + nt;
                    uint32_t bd = bbase + (uint32_t)((ki * 8 + ni) * 256 + lane * 8);
                    asm volatile("ld.shared.v2.b32 {%0,%1}, [%2];"
                                 : "=r"(bfr[nt][0]), "=r"(bfr[nt][1]) : "r"(bd));
                }
#pragma unroll
                for (int mt = 0; mt < 2; mt++)
#pragma unroll
                    for (int nt = 0; nt < 4; nt++)
                        mma16816(acc[mt][nt], afr[mt], bfr[nt]);
            }
        }

        // 5) build(c+1) into the opposite A buffer (overlaps tensor-pipe drain)
        if (c < 31) build(c + 1);
    }

    // ---- epilogue: write accumulators + bias ----
    {
        const int gid = lane >> 2, tig = lane & 3;
#pragma unroll
        for (int mt = 0; mt < 2; mt++) {
#pragma unroll
            for (int nt = 0; nt < 4; nt++) {
                int f = wn * 32 + nt * 8 + 2 * tig;
                float2 bv = *(const float2*)(bias + f);
                int r0 = (wm * 2 + mt) * 16 + gid;
                int r1 = r0 + 8;
                float* o0 = out + (((size_t)(b * HO) + (h0 + (r0 >> 6))) * WO + (r0 & 63)) * NF + f;
                float* o1 = out + (((size_t)(b * HO) + (h0 + (r1 >> 6))) * WO + (r1 & 63)) * NF + f;
                float2 v0, v1;
                v0.x = acc[mt][nt][0] + bv.x;  v0.y = acc[mt][nt][1] + bv.y;
                v1.x = acc[mt][nt][2] + bv.x;  v1.y = acc[mt][nt][3] + bv.y;
                *(float2*)o0 = v0;
                *(float2*)o1 = v1;
            }
        }
    }
}

// ---------------------------------------------------------------------------
extern "C" void kernel_launch(void* const* d_in, const int* in_sizes, int n_in,
                              void* d_out, int out_size)
{
    const float* x    = (const float*)d_in[0];   // (4,66,66,32)
    const float* cp   = (const float*)d_in[1];   // (64,32,3,3,17)
    const float* wsp  = (const float*)d_in[2];   // (64,32,3,3)
    const float* wsi  = (const float*)d_in[3];   // (64,32,3,3)
    const float* bias = (const float*)d_in[4];   // (64,)
    float* out        = (float*)d_out;           // (4,64,64,64)

    cudaFuncSetAttribute(kan_hmma_kernel, cudaFuncAttributeMaxDynamicSharedMemorySize, SM_TOTAL);

    {
        int n = 32 * KI * 8 * 32 * 4;
        build_bfrag_kernel<<<(n + 255) / 256, 256>>>(cp, wsp, wsi);
    }
    {
        int n = NB * NH * NW * NC;
        feat_kernel<<<(n + 255) / 256, 256>>>(x);
    }
    kan_hmma_kernel<<<128, 256, SM_TOTAL>>>(bias, out);
}

// round 10
// speedup vs baseline: 1.0031x; 1.0031x over previous
#include <cuda_runtime.h>
#include <cuda_fp16.h>
#include <cstdint>
#include <math.h>

// Problem constants
#define NB   4
#define NH   66
#define NW   66
#define NC   32
#define NF   64
#define HO   64
#define WO   64

// GEMM: per channel K = 176 (9 cij * 18 slots = 162 used, pad to 11 k16-steps)
#define KC        176
#define KI        11                  // k16 steps
#define A_BYTES   (128 * KC * 2)      // 45056 (fragment-major)
#define B_BYTES   (64 * KC * 2)       // 22528 (fragment-major)

// smem offsets
#define SM_A0     0
#define SM_A1     45056
#define SM_B0     90112
#define SM_B1     112640
#define SM_TOTAL  135168

// ---------------------------------------------------------------------------
// Device globals (no allocation allowed)
// B fragment images: [c][ki][ni][lane][4 halves]  (32 * 22528 B = 704 KB)
__device__ __align__(16) __half g_Bfrag[32 * (B_BYTES / 2)];
__device__ __align__(16) float4 g_featP[NC * NB * NH * NW];  // [c][b][h][w]: (t, silu, g-bits, 0)

// ---------------------------------------------------------------------------
__device__ __forceinline__ uint32_t smem_u32(const void* p) {
    uint32_t a;
    asm("{ .reg .u64 t; cvta.to.shared.u64 t, %1; cvt.u32.u64 %0, t; }" : "=r"(a) : "l"(p));
    return a;
}
__device__ __forceinline__ void cp_async16(uint32_t saddr, const void* gptr) {
    asm volatile("cp.async.cg.shared.global [%0], [%1], 16;"
                 :: "r"(saddr), "l"(__cvta_generic_to_global(gptr)) : "memory");
}
__device__ __forceinline__ void cp_commit() {
    asm volatile("cp.async.commit_group;" ::: "memory");
}
__device__ __forceinline__ void mma16816(float* d, const uint32_t* a, const uint32_t* b) {
    asm volatile("mma.sync.aligned.m16n8k16.row.col.f32.f16.f16.f32 "
                 "{%0,%1,%2,%3}, {%4,%5,%6,%7}, {%8,%9}, {%0,%1,%2,%3};"
                 : "+f"(d[0]), "+f"(d[1]), "+f"(d[2]), "+f"(d[3])
                 : "r"(a[0]), "r"(a[1]), "r"(a[2]), "r"(a[3]), "r"(b[0]), "r"(b[1]));
}

// A fragment-major byte address for logical element (pixel r, col):
//   mi=r>>4, row16=r&15, ki=col>>4, kk=col&15
//   lane = ((row16&7)<<2) | ((kk>>1)&3)
//   idx  = (kk&1) | (((row16>>3)&1)<<1) | (((kk>>3)&1)<<2)
//   addr = mi*5632 + ki*512 + lane*16 + idx*2
__device__ __forceinline__ uint32_t a_off(uint32_t base_t, int col) {
    int ki = col >> 4, kk = col & 15;
    return base_t + ki * 512 + (((kk >> 1) & 3) << 4) + ((kk & 1) << 1) + ((kk >> 3) << 3);
}

// ---------------------------------------------------------------------------
// P0: build B fragment images. One half per thread.
__global__ void build_bfrag_kernel(const float* __restrict__ cp,
                                   const float* __restrict__ w_spline,
                                   const float* __restrict__ w_silu)
{
    int idx = blockIdx.x * blockDim.x + threadIdx.x;
    if (idx >= 32 * KI * 8 * 32 * 4) return;
    int b_idx = idx & 3;
    int lane  = (idx >> 2) & 31;
    int ni    = (idx >> 7) & 7;
    int rest  = idx >> 10;
    int ki    = rest % KI;
    int c     = rest / KI;
    int gid   = lane >> 2, tig = lane & 3;
    int f     = ni * 8 + gid;
    int k     = ki * 16 + 2 * tig + (b_idx & 1) + ((b_idx >> 1) << 3);
    float v = 0.0f;
    if (k < 162) {
        int q = k / 18;
        int s = k - 18 * q;
        int iw = (f * 32 + c) * 9 + q;
        v = (s < 17) ? w_spline[iw] * cp[iw * 17 + s] : w_silu[iw];
    }
    g_Bfrag[idx] = __float2half_rn(v);
}

// ---------------------------------------------------------------------------
// P1: planar per-element features: (t, silu, g-as-int-bits, 0) at [c][b][h][w]
__global__ void feat_kernel(const float* __restrict__ x)
{
    int i = blockIdx.x * blockDim.x + threadIdx.x;
    if (i >= NB * NH * NW * NC) return;
    int c   = i & 31;
    int pos = i >> 5;
    float v  = x[i];
    float s  = v / (1.0f + __expf(-v));
    float xc = fminf(1.0f, fmaxf(-1.0f, v));
    float u  = (xc + 1.0f) * 8.0f;
    int   g  = (int)u;
    g = (g > 15) ? 15 : g;
    float t  = u - (float)g;
    g_featP[(size_t)c * (NB * NH * NW) + pos] = make_float4(t, s, __int_as_float(g), 0.0f);
}

// ---------------------------------------------------------------------------
// Main HMMA kernel: 128 blocks x 256 threads (1 block/SM).
// Block = (b, 2 output rows x 64 w) = 128 px. Warp (wm = wid>>1, wn = wid&1):
// M rows [32*wm, +32), N cols [32*wn, +32).
// Pipeline per channel c: wait B(c) -> sync -> prefetch B(c+1) -> MMA(c) -> build(c+1).
__global__ void __launch_bounds__(256, 1)
kan_hmma_kernel(const float* __restrict__ bias, float* __restrict__ out)
{
    extern __shared__ char smem[];
    const uint32_t sbase = smem_u32(smem);
    const int tid  = threadIdx.x;
    const int wid  = tid >> 5;
    const int lane = tid & 31;
    const int blk  = blockIdx.x;
    const int b    = blk >> 5;
    const int h0   = (blk & 31) * 2;

    // zero both A fragment buffers (cols never written stay 0 forever)
    {
        float4* az = (float4*)smem;
#pragma unroll 4
        for (int i = tid; i < (2 * A_BYTES) / 16; i += 256) az[i] = make_float4(0.f, 0.f, 0.f, 0.f);
    }
    // prefetch B(0) into B0
    for (int i = tid; i < B_BYTES / 16; i += 256)
        cp_async16(sbase + SM_B0 + i * 16, (const char*)g_Bfrag + i * 16);
    cp_commit();
    __syncthreads();   // A zeroing visible before scatter

    // scatter config: threads 0-127 -> pixel r, q 0..3; 128-255 -> same r, q 4..8
    const int r     = tid & 127;
    const int qbase = (tid >> 7) ? 4 : 0;
    const int qcnt  = (tid >> 7) ? 5 : 4;
    const int rh    = r >> 6, rw = r & 63;
    const int mi    = r >> 4, row16 = r & 15;
    const uint32_t base_t0 = (uint32_t)(mi * 5632 + ((row16 & 7) << 6) + (((row16 >> 3) & 1) << 2));

    const int wm = wid >> 1, wn = wid & 1;

    float acc[2][4][4];
#pragma unroll
    for (int mt = 0; mt < 2; mt++)
#pragma unroll
        for (int nt = 0; nt < 4; nt++)
#pragma unroll
            for (int e = 0; e < 4; e++) acc[mt][nt][e] = 0.0f;

    uint32_t gpack[2] = {0u, 0u};

    // build A(c) into buffer c&1 (zero stale slots from c-2 first)
    auto build = [&](int c) {
        char* Ab = smem + ((c & 1) ? SM_A1 : SM_A0);
#pragma unroll
        for (int qi = 0; qi < 5; qi++) {
            if (qi >= qcnt) break;
            int q  = qbase + qi;
            int ii = q / 3, jj = q - 3 * ii;
            float4 fv = __ldg(g_featP + ((size_t)(c * NB + b) * NH + (h0 + rh + ii)) * NW + (rw + jj));
            int g = __float_as_int(fv.z);
            if (c >= 2) {
                int gold = (gpack[c & 1] >> (4 * qi)) & 15;
                int oc   = q * 18 + gold;
                *(__half*)(Ab + a_off(base_t0, oc))     = __ushort_as_half((unsigned short)0);
                *(__half*)(Ab + a_off(base_t0, oc + 1)) = __ushort_as_half((unsigned short)0);
            }
            int col0 = q * 18 + g;
            *(__half*)(Ab + a_off(base_t0, col0))        = __float2half_rn(1.0f - fv.x);
            *(__half*)(Ab + a_off(base_t0, col0 + 1))    = __float2half_rn(fv.x);
            *(__half*)(Ab + a_off(base_t0, q * 18 + 17)) = __float2half_rn(fv.y);
            gpack[c & 1] = (gpack[c & 1] & ~(15u << (4 * qi))) | ((uint32_t)g << (4 * qi));
        }
    };

    build(0);

    for (int c = 0; c < 32; c++) {
        const int buf = c & 1;

        // 1) B(c) arrived (it is the only outstanding cp.async group here)
        asm volatile("cp.async.wait_group 0;" ::: "memory");
        // 2) barrier: build(c) visible; MMA(c-1) LDS of opposite buffers retired
        __syncthreads();
        // 3) issue prefetch B(c+1) into the opposite B buffer (now safe to overwrite)
        if (c < 31) {
            uint32_t bdst = sbase + (((c + 1) & 1) ? SM_B1 : SM_B0);
            const char* bsrc = (const char*)g_Bfrag + (size_t)(c + 1) * B_BYTES;
            for (int i = tid; i < B_BYTES / 16; i += 256)
                cp_async16(bdst + i * 16, bsrc + i * 16);
            cp_commit();
        }

        // 4) MMA(c): LDS fragments -> regs, accumulate
        {
            const uint32_t abase = sbase + (buf ? SM_A1 : SM_A0);
            const uint32_t bbase = sbase + (buf ? SM_B1 : SM_B0);
#pragma unroll
            for (int ki = 0; ki < KI; ki++) {
                uint32_t afr[2][4];
#pragma unroll
                for (int mt = 0; mt < 2; mt++) {
                    int mi_t = wm * 2 + mt;
                    uint32_t ad = abase + (uint32_t)((mi_t * KI + ki) * 512 + lane * 16);
                    asm volatile("ld.shared.v4.b32 {%0,%1,%2,%3}, [%4];"
                                 : "=r"(afr[mt][0]), "=r"(afr[mt][1]),
                                   "=r"(afr[mt][2]), "=r"(afr[mt][3]) : "r"(ad));
                }
                uint32_t bfr[4][2];
#pragma unroll
                for (int nt = 0; nt < 4; nt++) {
                    int ni = wn * 4 + nt;
                    uint32_t bd = bbase + (uint32_t)((ki * 8 + ni) * 256 + lane * 8);
                    asm volatile("ld.shared.v2.b32 {%0,%1}, [%2];"
                                 : "=r"(bfr[nt][0]), "=r"(bfr[nt][1]) : "r"(bd));
                }
#pragma unroll
                for (int mt = 0; mt < 2; mt++)
#pragma unroll
                    for (int nt = 0; nt < 4; nt++)
                        mma16816(acc[mt][nt], afr[mt], bfr[nt]);
            }
        }

        // 5) build(c+1) into the opposite A buffer (overlaps tensor-pipe drain)
        if (c < 31) build(c + 1);
    }

    // ---- epilogue: write accumulators + bias ----
    {
        const int gid = lane >> 2, tig = lane & 3;
#pragma unroll
        for (int mt = 0; mt < 2; mt++) {
#pragma unroll
            for (int nt = 0; nt < 4; nt++) {
                int f = wn * 32 + nt * 8 + 2 * tig;
                float2 bv = *(const float2*)(bias + f);
                int r0 = (wm * 2 + mt) * 16 + gid;
                int r1 = r0 + 8;
                float* o0 = out + (((size_t)(b * HO) + (h0 + (r0 >> 6))) * WO + (r0 & 63)) * NF + f;
                float* o1 = out + (((size_t)(b * HO) + (h0 + (r1 >> 6))) * WO + (r1 & 63)) * NF + f;
                float2 v0, v1;
                v0.x = acc[mt][nt][0] + bv.x;  v0.y = acc[mt][nt][1] + bv.y;
                v1.x = acc[mt][nt][2] + bv.x;  v1.y = acc[mt][nt][3] + bv.y;
                *(float2*)o0 = v0;
                *(float2*)o1 = v1;
            }
        }
    }
}

// ---------------------------------------------------------------------------
extern "C" void kernel_launch(void* const* d_in, const int* in_sizes, int n_in,
                              void* d_out, int out_size)
{
    const float* x    = (const float*)d_in[0];   // (4,66,66,32)
    const float* cp   = (const float*)d_in[1];   // (64,32,3,3,17)
    const float* wsp  = (const float*)d_in[2];   // (64,32,3,3)
    const float* wsi  = (const float*)d_in[3];   // (64,32,3,3)
    const float* bias = (const float*)d_in[4];   // (64,)
    float* out        = (float*)d_out;           // (4,64,64,64)

    cudaFuncSetAttribute(kan_hmma_kernel, cudaFuncAttributeMaxDynamicSharedMemorySize, SM_TOTAL);

    {
        int n = 32 * KI * 8 * 32 * 4;
        build_bfrag_kernel<<<(n + 255) / 256, 256>>>(cp, wsp, wsi);
    }
    {
        int n = NB * NH * NW * NC;
        feat_kernel<<<(n + 255) / 256, 256>>>(x);
    }
    kan_hmma_kernel<<<128, 256, SM_TOTAL>>>(bias, out);
}

// round 11
// speedup vs baseline: 1.0385x; 1.0353x over previous
#include <cuda_runtime.h>
#include <cuda_fp16.h>
#include <cstdint>
#include <math.h>

// Problem constants
#define NB   4
#define NH   66
#define NW   66
#define NC   32
#define NF   64
#define HO   64
#define WO   64

// GEMM: per channel K = 176 (9 cij * 18 slots = 162 used, pad to 11 k16-steps)
#define KC        176
#define KI        11                  // k16 steps
#define A_BYTES   (128 * KC * 2)      // 45056 (fragment-major)
#define B_BYTES   (64 * KC * 2)       // 22528 (fragment-major)
#define NOUT      (NB * HO * WO * NF) // 1048576

// smem offsets: two A fragment buffers only (B comes via LDG from L2)
#define SM_A0     0
#define SM_A1     45056
#define SM_TOTAL  90112

// ---------------------------------------------------------------------------
// Device globals (no allocation allowed)
// B fragment images: [c][ki][ni][lane][4 halves]  (32 * 22528 B = 704 KB, L2-resident)
__device__ __align__(16) __half g_Bfrag[32 * (B_BYTES / 2)];
__device__ __align__(16) float4 g_featP[NC * NB * NH * NW];  // [c][b][h][w]: (t, silu, g-bits, 0)
__device__ __align__(16) float  g_part0[NOUT];               // channel 0-15 partials
__device__ __align__(16) float  g_part1[NOUT];               // channel 16-31 partials

// ---------------------------------------------------------------------------
__device__ __forceinline__ uint32_t smem_u32(const void* p) {
    uint32_t a;
    asm("{ .reg .u64 t; cvta.to.shared.u64 t, %1; cvt.u32.u64 %0, t; }" : "=r"(a) : "l"(p));
    return a;
}
__device__ __forceinline__ void mma16816(float* d, const uint32_t* a, const uint32_t* b) {
    asm volatile("mma.sync.aligned.m16n8k16.row.col.f32.f16.f16.f32 "
                 "{%0,%1,%2,%3}, {%4,%5,%6,%7}, {%8,%9}, {%0,%1,%2,%3};"
                 : "+f"(d[0]), "+f"(d[1]), "+f"(d[2]), "+f"(d[3])
                 : "r"(a[0]), "r"(a[1]), "r"(a[2]), "r"(a[3]), "r"(b[0]), "r"(b[1]));
}

// A fragment-major byte address for logical element (pixel r, col):
//   mi=r>>4, row16=r&15, ki=col>>4, kk=col&15
//   lane = ((row16&7)<<2) | ((kk>>1)&3)
//   idx  = (kk&1) | (((row16>>3)&1)<<1) | (((kk>>3)&1)<<2)
__device__ __forceinline__ uint32_t a_off(uint32_t base_t, int col) {
    int ki = col >> 4, kk = col & 15;
    return base_t + ki * 512 + (((kk >> 1) & 3) << 4) + ((kk & 1) << 1) + ((kk >> 3) << 3);
}

// ---------------------------------------------------------------------------
// P0: build B fragment images. One half per thread.
__global__ void build_bfrag_kernel(const float* __restrict__ cp,
                                   const float* __restrict__ w_spline,
                                   const float* __restrict__ w_silu)
{
    int idx = blockIdx.x * blockDim.x + threadIdx.x;
    if (idx >= 32 * KI * 8 * 32 * 4) return;
    int b_idx = idx & 3;
    int lane  = (idx >> 2) & 31;
    int ni    = (idx >> 7) & 7;
    int rest  = idx >> 10;
    int ki    = rest % KI;
    int c     = rest / KI;
    int gid   = lane >> 2, tig = lane & 3;
    int f     = ni * 8 + gid;
    int k     = ki * 16 + 2 * tig + (b_idx & 1) + ((b_idx >> 1) << 3);
    float v = 0.0f;
    if (k < 162) {
        int q = k / 18;
        int s = k - 18 * q;
        int iw = (f * 32 + c) * 9 + q;
        v = (s < 17) ? w_spline[iw] * cp[iw * 17 + s] : w_silu[iw];
    }
    g_Bfrag[idx] = __float2half_rn(v);
}

// ---------------------------------------------------------------------------
// P1: planar per-element features: (t, silu, g-as-int-bits, 0) at [c][b][h][w]
__global__ void feat_kernel(const float* __restrict__ x)
{
    int i = blockIdx.x * blockDim.x + threadIdx.x;
    if (i >= NB * NH * NW * NC) return;
    int c   = i & 31;
    int pos = i >> 5;
    float v  = x[i];
    float s  = v / (1.0f + __expf(-v));
    float xc = fminf(1.0f, fmaxf(-1.0f, v));
    float u  = (xc + 1.0f) * 8.0f;
    int   g  = (int)u;
    g = (g > 15) ? 15 : g;
    float t  = u - (float)g;
    g_featP[(size_t)c * (NB * NH * NW) + pos] = make_float4(t, s, __int_as_float(g), 0.0f);
}

// ---------------------------------------------------------------------------
// Main HMMA kernel: 256 blocks x 256 threads, 2 blocks/SM.
// Block = (split s, b, 2 output rows) = 128 px, 16 channels [s*16, s*16+16).
// Warp (wm = wid>>1, wn = wid&1): M rows [32*wm, +32), N cols [32*wn, +32).
// Per channel: sync -> MMA(cc) [B via LDG, dist-1 prefetch] -> build(cc+1).
__global__ void __launch_bounds__(256, 2)
kan_hmma_kernel(float* __restrict__ part0, float* __restrict__ part1)
{
    extern __shared__ char smem[];
    const uint32_t sbase = smem_u32(smem);
    const int tid  = threadIdx.x;
    const int wid  = tid >> 5;
    const int lane = tid & 31;
    const int blk  = blockIdx.x;
    const int s    = blk >> 7;            // channel split
    const int b    = (blk >> 5) & 3;
    const int h0   = (blk & 31) * 2;
    const int c0   = s * 16;

    // zero both A fragment buffers (cols never written stay 0 forever)
    {
        float4* az = (float4*)smem;
#pragma unroll 4
        for (int i = tid; i < (2 * A_BYTES) / 16; i += 256) az[i] = make_float4(0.f, 0.f, 0.f, 0.f);
    }
    __syncthreads();   // A zeroing visible before scatter

    // scatter config: threads 0-127 -> pixel r, q 0..3; 128-255 -> same r, q 4..8
    const int r     = tid & 127;
    const int qbase = (tid >> 7) ? 4 : 0;
    const int qcnt  = (tid >> 7) ? 5 : 4;
    const int rh    = r >> 6, rw = r & 63;
    const int mi    = r >> 4, row16 = r & 15;
    const uint32_t base_t0 = (uint32_t)(mi * 5632 + ((row16 & 7) << 6) + (((row16 >> 3) & 1) << 2));

    const int wm = wid >> 1, wn = wid & 1;

    float acc[2][4][4];
#pragma unroll
    for (int mt = 0; mt < 2; mt++)
#pragma unroll
        for (int nt = 0; nt < 4; nt++)
#pragma unroll
            for (int e = 0; e < 4; e++) acc[mt][nt][e] = 0.0f;

    uint32_t gpack[2] = {0u, 0u};

    // build A(cc) into buffer cc&1 (zero stale slots from cc-2 first)
    auto build = [&](int cc) {
        char* Ab = smem + ((cc & 1) ? SM_A1 : SM_A0);
        int ca = c0 + cc;
#pragma unroll
        for (int qi = 0; qi < 5; qi++) {
            if (qi >= qcnt) break;
            int q  = qbase + qi;
            int ii = q / 3, jj = q - 3 * ii;
            float4 fv = __ldg(g_featP + ((size_t)(ca * NB + b) * NH + (h0 + rh + ii)) * NW + (rw + jj));
            int g = __float_as_int(fv.z);
            if (cc >= 2) {
                int gold = (gpack[cc & 1] >> (4 * qi)) & 15;
                int oc   = q * 18 + gold;
                *(__half*)(Ab + a_off(base_t0, oc))     = __ushort_as_half((unsigned short)0);
                *(__half*)(Ab + a_off(base_t0, oc + 1)) = __ushort_as_half((unsigned short)0);
            }
            int col0 = q * 18 + g;
            *(__half*)(Ab + a_off(base_t0, col0))        = __float2half_rn(1.0f - fv.x);
            *(__half*)(Ab + a_off(base_t0, col0 + 1))    = __float2half_rn(fv.x);
            *(__half*)(Ab + a_off(base_t0, q * 18 + 17)) = __float2half_rn(fv.y);
            gpack[cc & 1] = (gpack[cc & 1] & ~(15u << (4 * qi))) | ((uint32_t)g << (4 * qi));
        }
    };

    build(0);

    for (int cc = 0; cc < 16; cc++) {
        const int buf = cc & 1;
        // barrier: build(cc) visible; MMA(cc-1) LDS of same-parity buffer retired
        __syncthreads();

        // ---- MMA(cc): A frags via LDS, B frags via LDG (dist-1 prefetch) ----
        {
            const uint32_t abase = sbase + (buf ? SM_A1 : SM_A0);
            const __half*  Bc    = g_Bfrag + (size_t)(c0 + cc) * (B_BYTES / 2);
            uint2 bcur[4], bnxt[4];
#pragma unroll
            for (int nt = 0; nt < 4; nt++) {
                int ni = wn * 4 + nt;
                bcur[nt] = __ldg((const uint2*)(Bc + (size_t)(0 * 8 + ni) * 128 + lane * 4));
            }
#pragma unroll
            for (int ki = 0; ki < KI; ki++) {
                if (ki < KI - 1) {
#pragma unroll
                    for (int nt = 0; nt < 4; nt++) {
                        int ni = wn * 4 + nt;
                        bnxt[nt] = __ldg((const uint2*)(Bc + (size_t)((ki + 1) * 8 + ni) * 128 + lane * 4));
                    }
                }
                uint32_t afr[2][4];
#pragma unroll
                for (int mt = 0; mt < 2; mt++) {
                    int mi_t = wm * 2 + mt;
                    uint32_t ad = abase + (uint32_t)((mi_t * KI + ki) * 512 + lane * 16);
                    asm volatile("ld.shared.v4.b32 {%0,%1,%2,%3}, [%4];"
                                 : "=r"(afr[mt][0]), "=r"(afr[mt][1]),
                                   "=r"(afr[mt][2]), "=r"(afr[mt][3]) : "r"(ad));
                }
#pragma unroll
                for (int mt = 0; mt < 2; mt++)
#pragma unroll
                    for (int nt = 0; nt < 4; nt++)
                        mma16816(acc[mt][nt], afr[mt], (const uint32_t*)&bcur[nt]);
#pragma unroll
                for (int nt = 0; nt < 4; nt++) bcur[nt] = bnxt[nt];
            }
        }

        // ---- build(cc+1) into the opposite A buffer (overlaps tensor-pipe drain) ----
        if (cc < 15) build(cc + 1);
    }

    // ---- epilogue: write partial accumulators (no bias) ----
    {
        float* part = s ? part1 : part0;
        const int gid = lane >> 2, tig = lane & 3;
#pragma unroll
        for (int mt = 0; mt < 2; mt++) {
#pragma unroll
            for (int nt = 0; nt < 4; nt++) {
                int f = wn * 32 + nt * 8 + 2 * tig;
                int r0 = (wm * 2 + mt) * 16 + gid;
                int r1 = r0 + 8;
                float* o0 = part + (((size_t)(b * HO) + (h0 + (r0 >> 6))) * WO + (r0 & 63)) * NF + f;
                float* o1 = part + (((size_t)(b * HO) + (h0 + (r1 >> 6))) * WO + (r1 & 63)) * NF + f;
                *(float2*)o0 = make_float2(acc[mt][nt][0], acc[mt][nt][1]);
                *(float2*)o1 = make_float2(acc[mt][nt][2], acc[mt][nt][3]);
            }
        }
    }
}

// ---------------------------------------------------------------------------
// P3: out = part0 + part1 + bias  (float4 over 1M outputs)
__global__ void reduce_kernel(const float* __restrict__ bias, float* __restrict__ out)
{
    int i = blockIdx.x * blockDim.x + threadIdx.x;
    if (i >= NOUT / 4) return;
    float4 p0 = __ldg(((const float4*)g_part0) + i);
    float4 p1 = __ldg(((const float4*)g_part1) + i);
    float4 bv = __ldg(((const float4*)bias) + (i & 15));
    float4 o;
    o.x = p0.x + p1.x + bv.x;
    o.y = p0.y + p1.y + bv.y;
    o.z = p0.z + p1.z + bv.z;
    o.w = p0.w + p1.w + bv.w;
    ((float4*)out)[i] = o;
}

// ---------------------------------------------------------------------------
extern "C" void kernel_launch(void* const* d_in, const int* in_sizes, int n_in,
                              void* d_out, int out_size)
{
    const float* x    = (const float*)d_in[0];   // (4,66,66,32)
    const float* cp   = (const float*)d_in[1];   // (64,32,3,3,17)
    const float* wsp  = (const float*)d_in[2];   // (64,32,3,3)
    const float* wsi  = (const float*)d_in[3];   // (64,32,3,3)
    const float* bias = (const float*)d_in[4];   // (64,)
    float* out        = (float*)d_out;           // (4,64,64,64)

    cudaFuncSetAttribute(kan_hmma_kernel, cudaFuncAttributeMaxDynamicSharedMemorySize, SM_TOTAL);

    {
        int n = 32 * KI * 8 * 32 * 4;
        build_bfrag_kernel<<<(n + 255) / 256, 256>>>(cp, wsp, wsi);
    }
    {
        int n = NB * NH * NW * NC;
        feat_kernel<<<(n + 255) / 256, 256>>>(x);
    }

    float* p0;  cudaGetSymbolAddress((void**)&p0, g_part0);
    float* p1;  cudaGetSymbolAddress((void**)&p1, g_part1);
    kan_hmma_kernel<<<256, 256, SM_TOTAL>>>(p0, p1);

    reduce_kernel<<<(NOUT / 4 + 255) / 256, 256>>>(bias, out);
}